// round 13
// baseline (speedup 1.0000x reference)
#include <cuda_runtime.h>
#include <cuda_bf16.h>
#include <stdint.h>
#include <math.h>

#define N 8192
#define D 512
#define TAU 0.2f
// QSCALE^2 = log2(e)/TAU  ->  mma accumulator IS the exp2 argument
#define QSCALE 2.6857913f

#define BM 128
#define BN 128
#define THREADS 256           // 8 warps: 2 (M) x 4 (N), warp tile 64x32
#define ROWB 144              // 128 B data + 16 pad

#define A_BYTES (BM * ROWB)            // 18432
#define STAGE (2 * A_BYTES)            // A|B = 36864
#define NSTAGE 3
#define SMEM_TOTAL (NSTAGE * STAGE)    // 110592

#define NT12 4096
#define NTSYM 2080
#define NTOT (NT12 + 2 * NTSYM)        // 8256
#define GRIDX 304                      // 2 per SM

__device__ uint8_t g_h1q[N * D];      // e4m3, scaled by QSCALE
__device__ uint8_t g_h2q[N * D];
__device__ float g_S[4 * N];          // S11 | S12 | S21 | S22
__device__ float g_diag[N];           // dot scaled by QSCALE^2 = log2e/tau
__device__ unsigned int g_ctr;        // dynamic tile counter

// ---------------- helpers ----------------
__device__ __forceinline__ uint32_t smem_u32(const void* p) {
    uint32_t a;
    asm("{ .reg .u64 t; cvta.to.shared.u64 t, %1; cvt.u32.u64 %0, t; }" : "=r"(a) : "l"(p));
    return a;
}
#define CP_ASYNC16(dst, src) \
    asm volatile("cp.async.cg.shared.global [%0], [%1], 16;" :: "r"(dst), "l"(src))

__device__ __forceinline__ void ldm_x4(uint32_t* r, uint32_t addr) {
    asm volatile("ldmatrix.sync.aligned.m8n8.x4.shared.b16 {%0,%1,%2,%3}, [%4];"
                 : "=r"(r[0]), "=r"(r[1]), "=r"(r[2]), "=r"(r[3]) : "r"(addr));
}
__device__ __forceinline__ void mma_fp8(float* c, const uint32_t* a,
                                        uint32_t b0, uint32_t b1) {
    asm volatile(
        "mma.sync.aligned.m16n8k32.row.col.f32.e4m3.e4m3.f32 "
        "{%0,%1,%2,%3}, {%4,%5,%6,%7}, {%8,%9}, {%0,%1,%2,%3};"
        : "+f"(c[0]), "+f"(c[1]), "+f"(c[2]), "+f"(c[3])
        : "r"(a[0]), "r"(a[1]), "r"(a[2]), "r"(a[3]), "r"(b0), "r"(b1));
}
__device__ __forceinline__ float ex2(float x) {
    float r;
    asm("ex2.approx.f32 %0, %1;" : "=f"(r) : "f"(x));
    return r;
}
__device__ __forceinline__ uint32_t f4_to_e4m3(float x, float y, float z, float w) {
    uint16_t lo, hi;
    asm("cvt.rn.satfinite.e4m3x2.f32 %0, %1, %2;" : "=h"(lo) : "f"(y), "f"(x));
    asm("cvt.rn.satfinite.e4m3x2.f32 %0, %1, %2;" : "=h"(hi) : "f"(w), "f"(z));
    return (uint32_t)lo | ((uint32_t)hi << 16);
}

// tile index -> (mode, i0, j0). t<NT12: G12; then G11, G22 upper-tri (closed form).
__device__ __forceinline__ void decode_tile(int t, int& mode, int& i0, int& j0) {
    if (t < NT12) {
        mode = 0;
        i0 = (t >> 6) << 7;
        j0 = (t & 63) << 7;
    } else {
        int s = t - NT12;
        mode = (s >= NTSYM) ? 2 : 1;
        int k = (s >= NTSYM) ? s - NTSYM : s;
        float disc = 16641.0f - 8.0f * (float)k;
        int bi = (int)((129.0f - sqrtf(disc)) * 0.5f);
        int start = bi * 64 - ((bi * (bi - 1)) >> 1);
        if (k < start) { --bi; start = bi * 64 - ((bi * (bi - 1)) >> 1); }
        else if (bi < 63) {
            int nxt = (bi + 1) * 64 - (((bi + 1) * bi) >> 1);
            if (k >= nxt) { ++bi; start = nxt; }
        }
        i0 = bi << 7;
        j0 = (bi + (k - start)) << 7;
    }
}

// ---------------- pads: keep ncu -s 5 landing on gram_kernel ----------------
__global__ void pad_a_kernel() {}
__global__ void pad_b_kernel() {}

// ---------------- normalize -> fp8 (1 warp / row) ----------------
__global__ void normalize_kernel(const float* __restrict__ z1,
                                 const float* __restrict__ z2,
                                 float* __restrict__ out) {
    int row = blockIdx.x * 16 + (threadIdx.x >> 5);
    int lane = threadIdx.x & 31;
    const float* src;
    uint8_t* dst;
    if (row < N) { src = z1 + (size_t)row * D;       dst = g_h1q + (size_t)row * D; }
    else         { src = z2 + (size_t)(row - N) * D; dst = g_h2q + (size_t)(row - N) * D; }

    float4 v[4];
    float s = 0.0f;
    #pragma unroll
    for (int q = 0; q < 4; ++q) {
        v[q] = ((const float4*)src)[lane + q * 32];
        s += v[q].x * v[q].x + v[q].y * v[q].y + v[q].z * v[q].z + v[q].w * v[q].w;
    }
    #pragma unroll
    for (int o = 16; o; o >>= 1) s += __shfl_xor_sync(0xFFFFFFFFu, s, o);
    float inv = QSCALE * rsqrtf(s);

    #pragma unroll
    for (int q = 0; q < 4; ++q) {
        uint32_t pk = f4_to_e4m3(v[q].x * inv, v[q].y * inv, v[q].z * inv, v[q].w * inv);
        *(uint32_t*)&dst[4 * (lane + q * 32)] = pk;
    }

    int gidx = blockIdx.x * blockDim.x + threadIdx.x;
    if (gidx < 4 * N) g_S[gidx] = 0.0f;
    if (gidx == 0) { out[0] = 0.0f; g_ctr = 0u; }
}

// ---------------- persistent fused QMMA Gram (dynamic tile stealing) ----------
__global__ __launch_bounds__(THREADS, 2) void gram_kernel() {
    __shared__ int tq[2][3];                  // {mode, i0, j0} per slot
    __shared__ int tvalid[2];
    extern __shared__ __align__(16) char smem[];
    const uint32_t sb = smem_u32(smem);

    const int tid = threadIdx.x;
    const int wid = tid >> 5;
    const int lane = tid & 31;
    const int wm = wid >> 2;                  // 0..1
    const int wn = wid & 3;                   // 0..3

    auto claim = [&](int slot) {
        if (tid == 0) {
            unsigned t = atomicAdd(&g_ctr, 1u);
            if (t < NTOT) {
                int m, a, b;
                decode_tile((int)t, m, a, b);
                tq[slot][0] = m; tq[slot][1] = a; tq[slot][2] = b;
                tvalid[slot] = 1;
            } else {
                tvalid[slot] = 0;
            }
        }
    };

    auto issue_chunk = [&](int mL, int i0L, int j0L, int ko, int buf) {
        const uint8_t* Ap = (mL == 2) ? g_h2q : g_h1q;
        const uint8_t* Bp = (mL == 1) ? g_h1q : g_h2q;
        const uint32_t base = sb + buf * STAGE;
        const int kOff = ko * 128;
        #pragma unroll
        for (int q = 0; q < 4; ++q) {
            int ch = tid + q * 256;
            int row = ch >> 3;
            int ci = ch & 7;
            CP_ASYNC16(base + row * ROWB + ci * 16,
                       (const char*)(Ap + (size_t)(i0L + row) * D + kOff + ci * 16));
            CP_ASYNC16(base + A_BYTES + row * ROWB + ci * 16,
                       (const char*)(Bp + (size_t)(j0L + row) * D + kOff + ci * 16));
        }
        asm volatile("cp.async.commit_group;");
    };

    const uint32_t aLane = (uint32_t)((wm * 64 + (lane & 15)) * ROWB +
                                      ((lane >> 4) & 1) * 16);
    const uint32_t bLane = (uint32_t)((wn * 32 + (lane & 7) + ((lane >> 4) << 3)) * ROWB +
                                      ((lane >> 3) & 1) * 16 + A_BYTES);

    float c[4][4][4];
    auto compute_chunk = [&](int buf) {
        const uint32_t stg = sb + buf * STAGE;
        #pragma unroll
        for (int ks = 0; ks < 4; ++ks) {
            uint32_t a[4][4], b[2][4];
            #pragma unroll
            for (int mi = 0; mi < 4; ++mi)
                ldm_x4(a[mi], stg + aLane + mi * 16 * ROWB + ks * 32);
            #pragma unroll
            for (int p = 0; p < 2; ++p)
                ldm_x4(b[p], stg + bLane + p * 16 * ROWB + ks * 32);
            #pragma unroll
            for (int mi = 0; mi < 4; ++mi)
                #pragma unroll
                for (int p = 0; p < 2; ++p) {
                    mma_fp8(c[mi][2 * p],     a[mi], b[p][0], b[p][1]);
                    mma_fp8(c[mi][2 * p + 1], a[mi], b[p][2], b[p][3]);
                }
        }
    };

    // prologue: claim tiles 0 and 1; issue tile0 chunks 0,1
    claim(0);
    __syncthreads();
    claim(1);
    {
        int m0 = tq[0][0], a0 = tq[0][1], b0 = tq[0][2];
        issue_chunk(m0, a0, b0, 0, 0);
        issue_chunk(m0, a0, b0, 1, 1);
    }
    int ib = 2;                               // next issue buffer (mod 3)
    int cb = 0;                               // next compute buffer (mod 3)
    int slot = 0;

    for (;;) {
        const int mC = tq[slot][0];
        const int i0 = tq[slot][1];
        const int j0 = tq[slot][2];
        #pragma unroll
        for (int mi = 0; mi < 4; ++mi)
            #pragma unroll
            for (int ni = 0; ni < 4; ++ni)
                #pragma unroll
                for (int q = 0; q < 4; ++q) c[mi][ni][q] = 0.0f;

        // step0: compute chunk0, issue cur chunk2
        asm volatile("cp.async.wait_group 1;" ::: "memory");
        __syncthreads();
        issue_chunk(mC, i0, j0, 2, ib); ib = (ib == 2) ? 0 : ib + 1;
        compute_chunk(cb); cb = (cb == 2) ? 0 : cb + 1;

        // step1: compute chunk1, issue cur chunk3, claim tile k+2 into own slot
        asm volatile("cp.async.wait_group 1;" ::: "memory");
        __syncthreads();
        issue_chunk(mC, i0, j0, 3, ib); ib = (ib == 2) ? 0 : ib + 1;
        claim(slot);
        compute_chunk(cb); cb = (cb == 2) ? 0 : cb + 1;

        // step2: compute chunk2, issue next tile chunk0
        asm volatile("cp.async.wait_group 1;" ::: "memory");
        __syncthreads();
        const int vn = tvalid[slot ^ 1];
        int mN = 0, iN = 0, jN = 0;
        if (vn) {
            mN = tq[slot ^ 1][0]; iN = tq[slot ^ 1][1]; jN = tq[slot ^ 1][2];
            issue_chunk(mN, iN, jN, 0, ib); ib = (ib == 2) ? 0 : ib + 1;
        }
        compute_chunk(cb); cb = (cb == 2) ? 0 : cb + 1;

        // step3: compute chunk3, issue next tile chunk1
        if (vn) asm volatile("cp.async.wait_group 1;" ::: "memory");
        else    asm volatile("cp.async.wait_group 0;" ::: "memory");
        __syncthreads();
        if (vn) { issue_chunk(mN, iN, jN, 1, ib); ib = (ib == 2) ? 0 : ib + 1; }
        compute_chunk(cb); cb = (cb == 2) ? 0 : cb + 1;

        // ---- epilogue (accumulator already in exp2 units) ----
        const bool sym = (mC != 0);
        float* Srow;
        float* Scol;
        if      (mC == 0) { Srow = g_S + N;     Scol = g_S + 2 * N; }
        else if (mC == 1) { Srow = g_S;         Scol = g_S;         }
        else              { Srow = g_S + 3 * N; Scol = g_S + 3 * N; }

        float rsum[4][2];
        float csum[4][2];
        #pragma unroll
        for (int q = 0; q < 4; ++q) {
            rsum[q][0] = rsum[q][1] = 0.0f;
            csum[q][0] = csum[q][1] = 0.0f;
        }

        if (i0 != j0) {
            #pragma unroll
            for (int mi = 0; mi < 4; ++mi)
                #pragma unroll
                for (int ni = 0; ni < 4; ++ni)
                    #pragma unroll
                    for (int q = 0; q < 4; ++q) {
                        float e = ex2(c[mi][ni][q]);
                        rsum[mi][q >> 1] += e;
                        csum[ni][q & 1]  += e;
                    }
        } else {
            #pragma unroll
            for (int mi = 0; mi < 4; ++mi) {
                const int gr0 = i0 + wm * 64 + mi * 16 + (lane >> 2);
                #pragma unroll
                for (int ni = 0; ni < 4; ++ni) {
                    const int gc0 = j0 + wn * 32 + ni * 8 + (lane & 3) * 2;
                    #pragma unroll
                    for (int q = 0; q < 4; ++q) {
                        const int gr = gr0 + ((q >> 1) << 3);
                        const int gc = gc0 + (q & 1);
                        float dot = c[mi][ni][q];
                        float e = ex2(dot);
                        rsum[mi][q >> 1] += ((!sym) || (gc >= gr)) ? e : 0.0f;
                        csum[ni][q & 1]  += ((!sym) || (gc > gr))  ? e : 0.0f;
                        if (mC == 0 && gr == gc) g_diag[gr] = dot;
                    }
                }
            }
        }

        #pragma unroll
        for (int mi = 0; mi < 4; ++mi)
            #pragma unroll
            for (int h = 0; h < 2; ++h) {
                float v = rsum[mi][h];
                v += __shfl_xor_sync(0xFFFFFFFFu, v, 1);
                v += __shfl_xor_sync(0xFFFFFFFFu, v, 2);
                if ((lane & 3) == 0)
                    atomicAdd(&Srow[i0 + wm * 64 + mi * 16 + (lane >> 2) + h * 8], v);
            }
        #pragma unroll
        for (int ni = 0; ni < 4; ++ni)
            #pragma unroll
            for (int h = 0; h < 2; ++h) {
                float v = csum[ni][h];
                v += __shfl_xor_sync(0xFFFFFFFFu, v, 4);
                v += __shfl_xor_sync(0xFFFFFFFFu, v, 8);
                v += __shfl_xor_sync(0xFFFFFFFFu, v, 16);
                if (lane < 4)
                    atomicAdd(&Scol[j0 + wn * 32 + ni * 8 + lane * 2 + h], v);
            }

        slot ^= 1;
        if (!vn) break;
    }
    asm volatile("cp.async.wait_group 0;" ::: "memory");
}

// ---------------- finalize ----------------
__global__ void finalize_kernel(float* __restrict__ out) {
    int i = blockIdx.x * blockDim.x + threadIdx.x;
    float v = 0.0f;
    if (i < N) {
        const float E5 = 148.41315910257660f;   // exp(1/TAU)
        float d = g_diag[i] * 0.69314718055994531f;  // dot*log2e/tau * ln2 = dot/tau
        float den1 = g_S[i]         + g_S[N + i]     - E5;
        float den2 = g_S[3 * N + i] + g_S[2 * N + i] - E5;
        v = 0.5f * ((__logf(den1) - d) + (__logf(den2) - d));
    }
    #pragma unroll
    for (int o = 16; o; o >>= 1) v += __shfl_xor_sync(0xFFFFFFFFu, v, o);
    __shared__ float ws[8];
    if ((threadIdx.x & 31) == 0) ws[threadIdx.x >> 5] = v;
    __syncthreads();
    if (threadIdx.x == 0) {
        float s = 0.0f;
        #pragma unroll
        for (int q = 0; q < 8; ++q) s += ws[q];
        atomicAdd(out, s);
    }
}

extern "C" void kernel_launch(void* const* d_in, const int* in_sizes, int n_in,
                              void* d_out, int out_size) {
    const float* z1 = (const float*)d_in[0];
    const float* z2 = (const float*)d_in[1];
    float* out = (float*)d_out;

    static bool cfgd = false;
    if (!cfgd) {
        cudaFuncSetAttribute(gram_kernel,
                             cudaFuncAttributeMaxDynamicSharedMemorySize, SMEM_TOTAL);
        cfgd = true;
    }

    pad_a_kernel<<<1, 32>>>();
    pad_b_kernel<<<1, 32>>>();
    normalize_kernel<<<2 * N / 16, 512>>>(z1, z2, out);
    gram_kernel<<<GRIDX, THREADS, SMEM_TOTAL>>>();
    finalize_kernel<<<N / 256, 256>>>(out);
}

// round 14
// speedup vs baseline: 1.0627x; 1.0627x over previous
#include <cuda_runtime.h>
#include <cuda_bf16.h>
#include <stdint.h>
#include <math.h>

#define N 8192
#define D 512
#define TAU 0.2f
// QSCALE^2 = log2(e)/TAU  ->  mma accumulator IS the exp2 argument
#define QSCALE 2.6857913f

#define BM 128
#define BN 128
#define THREADS 256           // 8 warps: 2 (M) x 4 (N), warp tile 64x32
#define ROWB 144              // 128 B data + 16 pad

#define A_BYTES (BM * ROWB)            // 18432
#define STAGE (2 * A_BYTES)            // A|B = 36864
#define NSTAGE 3
#define SMEM_TOTAL (NSTAGE * STAGE)    // 110592

#define NT12 4096
#define NTSYM 2080
#define NTOT (NT12 + 2 * NTSYM)        // 8256

__device__ uint8_t g_h1q[N * D];      // e4m3, scaled by QSCALE
__device__ uint8_t g_h2q[N * D];
__device__ float g_S[4 * N];          // S11 | S12 | S21 | S22
__device__ float g_diag[N];           // dot scaled by log2e/tau

// ---------------- helpers ----------------
__device__ __forceinline__ uint32_t smem_u32(const void* p) {
    uint32_t a;
    asm("{ .reg .u64 t; cvta.to.shared.u64 t, %1; cvt.u32.u64 %0, t; }" : "=r"(a) : "l"(p));
    return a;
}
#define CP_ASYNC16(dst, src) \
    asm volatile("cp.async.cg.shared.global [%0], [%1], 16;" :: "r"(dst), "l"(src))

__device__ __forceinline__ void ldm_x4(uint32_t* r, uint32_t addr) {
    asm volatile("ldmatrix.sync.aligned.m8n8.x4.shared.b16 {%0,%1,%2,%3}, [%4];"
                 : "=r"(r[0]), "=r"(r[1]), "=r"(r[2]), "=r"(r[3]) : "r"(addr));
}
__device__ __forceinline__ void mma_fp8(float* c, const uint32_t* a,
                                        uint32_t b0, uint32_t b1) {
    asm volatile(
        "mma.sync.aligned.m16n8k32.row.col.f32.e4m3.e4m3.f32 "
        "{%0,%1,%2,%3}, {%4,%5,%6,%7}, {%8,%9}, {%0,%1,%2,%3};"
        : "+f"(c[0]), "+f"(c[1]), "+f"(c[2]), "+f"(c[3])
        : "r"(a[0]), "r"(a[1]), "r"(a[2]), "r"(a[3]), "r"(b0), "r"(b1));
}
__device__ __forceinline__ float ex2(float x) {
    float r;
    asm("ex2.approx.f32 %0, %1;" : "=f"(r) : "f"(x));
    return r;
}
__device__ __forceinline__ uint32_t f4_to_e4m3(float x, float y, float z, float w) {
    uint16_t lo, hi;
    asm("cvt.rn.satfinite.e4m3x2.f32 %0, %1, %2;" : "=h"(lo) : "f"(y), "f"(x));
    asm("cvt.rn.satfinite.e4m3x2.f32 %0, %1, %2;" : "=h"(hi) : "f"(w), "f"(z));
    return (uint32_t)lo | ((uint32_t)hi << 16);
}

// tile index -> (mode, i0, j0). t<NT12: G12; then G11, G22 upper-tri (closed form).
__device__ __forceinline__ void decode_tile(int t, int& mode, int& i0, int& j0) {
    if (t < NT12) {
        mode = 0;
        i0 = (t >> 6) << 7;
        j0 = (t & 63) << 7;
    } else {
        int s = t - NT12;
        mode = (s >= NTSYM) ? 2 : 1;
        int k = (s >= NTSYM) ? s - NTSYM : s;
        float disc = 16641.0f - 8.0f * (float)k;
        int bi = (int)((129.0f - sqrtf(disc)) * 0.5f);
        int start = bi * 64 - ((bi * (bi - 1)) >> 1);
        if (k < start) { --bi; start = bi * 64 - ((bi * (bi - 1)) >> 1); }
        else if (bi < 63) {
            int nxt = (bi + 1) * 64 - (((bi + 1) * bi) >> 1);
            if (k >= nxt) { ++bi; start = nxt; }
        }
        i0 = bi << 7;
        j0 = (bi + (k - start)) << 7;
    }
}

// ---------------- pads: keep ncu -s 5 landing on gram_kernel ----------------
__global__ void pad_a_kernel() {}
__global__ void pad_b_kernel() {}

// ---------------- normalize -> fp8 (1 warp / row) ----------------
__global__ void normalize_kernel(const float* __restrict__ z1,
                                 const float* __restrict__ z2,
                                 float* __restrict__ out) {
    int row = blockIdx.x * 16 + (threadIdx.x >> 5);
    int lane = threadIdx.x & 31;
    const float* src;
    uint8_t* dst;
    if (row < N) { src = z1 + (size_t)row * D;       dst = g_h1q + (size_t)row * D; }
    else         { src = z2 + (size_t)(row - N) * D; dst = g_h2q + (size_t)(row - N) * D; }

    float4 v[4];
    float s = 0.0f;
    #pragma unroll
    for (int q = 0; q < 4; ++q) {
        v[q] = ((const float4*)src)[lane + q * 32];
        s += v[q].x * v[q].x + v[q].y * v[q].y + v[q].z * v[q].z + v[q].w * v[q].w;
    }
    #pragma unroll
    for (int o = 16; o; o >>= 1) s += __shfl_xor_sync(0xFFFFFFFFu, s, o);
    float inv = QSCALE * rsqrtf(s);

    #pragma unroll
    for (int q = 0; q < 4; ++q) {
        uint32_t pk = f4_to_e4m3(v[q].x * inv, v[q].y * inv, v[q].z * inv, v[q].w * inv);
        *(uint32_t*)&dst[4 * (lane + q * 32)] = pk;
    }

    int gidx = blockIdx.x * blockDim.x + threadIdx.x;
    if (gidx < 4 * N) g_S[gidx] = 0.0f;
    if (gidx == 0) out[0] = 0.0f;
}

// ---------------- fused QMMA Gram + exp + reductions (exact 1-D tile grid) ----
__global__ __launch_bounds__(THREADS, 2) void gram_kernel() {
    int mode, i0, j0;
    decode_tile((int)blockIdx.x, mode, i0, j0);
    const bool sym = (mode != 0);

    const uint8_t* __restrict__ Ap = (mode == 2) ? g_h2q : g_h1q;
    const uint8_t* __restrict__ Bp = (mode == 1) ? g_h1q : g_h2q;
    float* Srow;
    float* Scol;
    if      (mode == 0) { Srow = g_S + N;     Scol = g_S + 2 * N; }
    else if (mode == 1) { Srow = g_S;         Scol = g_S;         }
    else                { Srow = g_S + 3 * N; Scol = g_S + 3 * N; }

    const int tid = threadIdx.x;
    const int wid = tid >> 5;
    const int lane = tid & 31;
    const int wm = wid >> 2;                  // 0..1
    const int wn = wid & 3;                   // 0..3

    extern __shared__ __align__(16) char smem[];
    const uint32_t sb = smem_u32(smem);

    // ---- strength-reduced loader bases (zero per-chunk arithmetic) ----
    // ci = tid&7 is q-invariant; row = tid>>3 + 32q.
    const int lr = tid >> 3;                  // base row 0..31
    const int lc16 = (tid & 7) * 16;          // byte column
    const char* aSrc = (const char*)(Ap + (size_t)(i0 + lr) * D) + lc16;
    const char* bSrc = (const char*)(Bp + (size_t)(j0 + lr) * D) + lc16;
    const uint32_t aDst = sb + lr * ROWB + lc16;
    const uint32_t bDst = aDst + A_BYTES;

    // issue one K-chunk: all offsets are compile-time constants off the bases
    auto load_stage = [&](int kt, int buf) {
        const int kOff = kt * 128;
        const uint32_t so = buf * STAGE;
        #pragma unroll
        for (int q = 0; q < 4; ++q) {
            CP_ASYNC16(aDst + so + q * (32 * ROWB), aSrc + kOff + q * (32 * D));
            CP_ASYNC16(bDst + so + q * (32 * ROWB), bSrc + kOff + q * (32 * D));
        }
        asm volatile("cp.async.commit_group;");
    };

    float c[4][4][4];
    #pragma unroll
    for (int mi = 0; mi < 4; ++mi)
        #pragma unroll
        for (int ni = 0; ni < 4; ++ni)
            #pragma unroll
            for (int q = 0; q < 4; ++q) c[mi][ni][q] = 0.0f;

    load_stage(0, 0);
    load_stage(1, 1);

    const uint32_t aLane = (uint32_t)((wm * 64 + (lane & 15)) * ROWB +
                                      ((lane >> 4) & 1) * 16);
    const uint32_t bLane = (uint32_t)((wn * 32 + (lane & 7) + ((lane >> 4) << 3)) * ROWB +
                                      ((lane >> 3) & 1) * 16 + A_BYTES);

    #pragma unroll
    for (int kt = 0; kt < 4; ++kt) {          // 4 K-chunks of 128 fp8
        const int buf = kt % NSTAGE;
        if (kt < 3) asm volatile("cp.async.wait_group 1;" ::: "memory");
        else        asm volatile("cp.async.wait_group 0;" ::: "memory");
        __syncthreads();
        if (kt + 2 < 4) load_stage(kt + 2, (kt + 2) % NSTAGE);

        const uint32_t stg = sb + buf * STAGE;
        #pragma unroll
        for (int ks = 0; ks < 4; ++ks) {      // 4 x k32 fp8 per chunk
            uint32_t a[4][4], b[2][4];
            #pragma unroll
            for (int mi = 0; mi < 4; ++mi)
                ldm_x4(a[mi], stg + aLane + mi * 16 * ROWB + ks * 32);
            #pragma unroll
            for (int p = 0; p < 2; ++p)
                ldm_x4(b[p], stg + bLane + p * 16 * ROWB + ks * 32);
            #pragma unroll
            for (int mi = 0; mi < 4; ++mi)
                #pragma unroll
                for (int p = 0; p < 2; ++p) {
                    mma_fp8(c[mi][2 * p],     a[mi], b[p][0], b[p][1]);
                    mma_fp8(c[mi][2 * p + 1], a[mi], b[p][2], b[p][3]);
                }
        }
    }

    // ---- epilogue (accumulator already in exp2 units) ----
    float rsum[4][2];
    float csum[4][2];
    #pragma unroll
    for (int q = 0; q < 4; ++q) {
        rsum[q][0] = rsum[q][1] = 0.0f;
        csum[q][0] = csum[q][1] = 0.0f;
    }

    if (i0 != j0) {
        #pragma unroll
        for (int mi = 0; mi < 4; ++mi)
            #pragma unroll
            for (int ni = 0; ni < 4; ++ni)
                #pragma unroll
                for (int q = 0; q < 4; ++q) {
                    float e = ex2(c[mi][ni][q]);
                    rsum[mi][q >> 1] += e;
                    csum[ni][q & 1]  += e;
                }
    } else {
        #pragma unroll
        for (int mi = 0; mi < 4; ++mi) {
            const int gr0 = i0 + wm * 64 + mi * 16 + (lane >> 2);
            #pragma unroll
            for (int ni = 0; ni < 4; ++ni) {
                const int gc0 = j0 + wn * 32 + ni * 8 + (lane & 3) * 2;
                #pragma unroll
                for (int q = 0; q < 4; ++q) {
                    const int gr = gr0 + ((q >> 1) << 3);
                    const int gc = gc0 + (q & 1);
                    float dot = c[mi][ni][q];
                    float e = ex2(dot);
                    rsum[mi][q >> 1] += ((!sym) || (gc >= gr)) ? e : 0.0f;
                    csum[ni][q & 1]  += ((!sym) || (gc > gr))  ? e : 0.0f;
                    if (mode == 0 && gr == gc) g_diag[gr] = dot;
                }
            }
        }
    }

    #pragma unroll
    for (int mi = 0; mi < 4; ++mi)
        #pragma unroll
        for (int h = 0; h < 2; ++h) {
            float v = rsum[mi][h];
            v += __shfl_xor_sync(0xFFFFFFFFu, v, 1);
            v += __shfl_xor_sync(0xFFFFFFFFu, v, 2);
            if ((lane & 3) == 0)
                atomicAdd(&Srow[i0 + wm * 64 + mi * 16 + (lane >> 2) + h * 8], v);
        }

    #pragma unroll
    for (int ni = 0; ni < 4; ++ni)
        #pragma unroll
        for (int h = 0; h < 2; ++h) {
            float v = csum[ni][h];
            v += __shfl_xor_sync(0xFFFFFFFFu, v, 4);
            v += __shfl_xor_sync(0xFFFFFFFFu, v, 8);
            v += __shfl_xor_sync(0xFFFFFFFFu, v, 16);
            if (lane < 4)
                atomicAdd(&Scol[j0 + wn * 32 + ni * 8 + lane * 2 + h], v);
        }
}

// ---------------- finalize ----------------
__global__ void finalize_kernel(float* __restrict__ out) {
    int i = blockIdx.x * blockDim.x + threadIdx.x;
    float v = 0.0f;
    if (i < N) {
        const float E5 = 148.41315910257660f;        // exp(1/TAU)
        float d = g_diag[i] * 0.69314718055994531f;  // (dot*log2e/tau)*ln2 = dot/tau
        float den1 = g_S[i]         + g_S[N + i]     - E5;
        float den2 = g_S[3 * N + i] + g_S[2 * N + i] - E5;
        v = 0.5f * ((__logf(den1) - d) + (__logf(den2) - d));
    }
    #pragma unroll
    for (int o = 16; o; o >>= 1) v += __shfl_xor_sync(0xFFFFFFFFu, v, o);
    __shared__ float ws[8];
    if ((threadIdx.x & 31) == 0) ws[threadIdx.x >> 5] = v;
    __syncthreads();
    if (threadIdx.x == 0) {
        float s = 0.0f;
        #pragma unroll
        for (int q = 0; q < 8; ++q) s += ws[q];
        atomicAdd(out, s);
    }
}

extern "C" void kernel_launch(void* const* d_in, const int* in_sizes, int n_in,
                              void* d_out, int out_size) {
    const float* z1 = (const float*)d_in[0];
    const float* z2 = (const float*)d_in[1];
    float* out = (float*)d_out;

    static bool cfgd = false;
    if (!cfgd) {
        cudaFuncSetAttribute(gram_kernel,
                             cudaFuncAttributeMaxDynamicSharedMemorySize, SMEM_TOTAL);
        cfgd = true;
    }

    pad_a_kernel<<<1, 32>>>();
    pad_b_kernel<<<1, 32>>>();
    normalize_kernel<<<2 * N / 16, 512>>>(z1, z2, out);
    gram_kernel<<<NTOT, THREADS, SMEM_TOTAL>>>();
    finalize_kernel<<<N / 256, 256>>>(out);
}

// round 15
// speedup vs baseline: 1.1322x; 1.0653x over previous
#include <cuda_runtime.h>
#include <cuda_bf16.h>
#include <stdint.h>
#include <math.h>

#define N 8192
#define D 512
#define TAU 0.2f
// QSCALE^2 = log2(e)/TAU  ->  mma accumulator IS the exp2 argument
#define QSCALE 2.6857913f

#define BM 128
#define BN 128
#define THREADS 256           // 8 warps: 2 (M) x 4 (N), warp tile 64x32
#define ROWB 144              // 128 B data + 16 pad

#define A_BYTES (BM * ROWB)            // 18432
#define STAGE (2 * A_BYTES)            // A|B = 36864
#define NSTAGE 3
#define SMEM_TOTAL (NSTAGE * STAGE)    // 110592

#define NT12 4096
#define NTSYM 2080
#define NTOT (NT12 + 2 * NTSYM)        // 8256

__device__ uint8_t g_h1q[N * D];      // e4m3, scaled by QSCALE
__device__ uint8_t g_h2q[N * D];
__device__ float g_S[4 * N];          // S11 | S12 | S21 | S22
__device__ float g_diag[N];           // dot scaled by log2e/tau

// ---------------- helpers ----------------
__device__ __forceinline__ uint32_t smem_u32(const void* p) {
    uint32_t a;
    asm("{ .reg .u64 t; cvta.to.shared.u64 t, %1; cvt.u32.u64 %0, t; }" : "=r"(a) : "l"(p));
    return a;
}
#define CP_ASYNC16(dst, src) \
    asm volatile("cp.async.cg.shared.global [%0], [%1], 16;" :: "r"(dst), "l"(src))

__device__ __forceinline__ void ldm_x4(uint32_t* r, uint32_t addr) {
    asm volatile("ldmatrix.sync.aligned.m8n8.x4.shared.b16 {%0,%1,%2,%3}, [%4];"
                 : "=r"(r[0]), "=r"(r[1]), "=r"(r[2]), "=r"(r[3]) : "r"(addr));
}
__device__ __forceinline__ void mma_fp8(float* c, const uint32_t* a,
                                        uint32_t b0, uint32_t b1) {
    asm volatile(
        "mma.sync.aligned.m16n8k32.row.col.f32.e4m3.e4m3.f32 "
        "{%0,%1,%2,%3}, {%4,%5,%6,%7}, {%8,%9}, {%0,%1,%2,%3};"
        : "+f"(c[0]), "+f"(c[1]), "+f"(c[2]), "+f"(c[3])
        : "r"(a[0]), "r"(a[1]), "r"(a[2]), "r"(a[3]), "r"(b0), "r"(b1));
}
__device__ __forceinline__ float ex2(float x) {
    float r;
    asm("ex2.approx.f32 %0, %1;" : "=f"(r) : "f"(x));
    return r;
}
// packed f16x2 epilogue ops
__device__ __forceinline__ uint32_t pack_h2(float lo, float hi) {
    uint32_t d;                            // first src operand -> upper half
    asm("cvt.rn.f16x2.f32 %0, %1, %2;" : "=r"(d) : "f"(hi), "f"(lo));
    return d;
}
__device__ __forceinline__ uint32_t ex2_h2(uint32_t a) {
    uint32_t d;
    asm("ex2.approx.f16x2 %0, %1;" : "=r"(d) : "r"(a));
    return d;
}
__device__ __forceinline__ uint32_t hadd2(uint32_t a, uint32_t b) {
    uint32_t d;
    asm("add.rn.f16x2 %0, %1, %2;" : "=r"(d) : "r"(a), "r"(b));
    return d;
}
__device__ __forceinline__ float2 unpack_h2(uint32_t a) {
    float lo, hi;
    asm("{.reg .f16 l,h; mov.b32 {l,h}, %2; cvt.f32.f16 %0, l; cvt.f32.f16 %1, h;}"
        : "=f"(lo), "=f"(hi) : "r"(a));
    return make_float2(lo, hi);
}
__device__ __forceinline__ uint32_t f4_to_e4m3(float x, float y, float z, float w) {
    uint16_t lo, hi;
    asm("cvt.rn.satfinite.e4m3x2.f32 %0, %1, %2;" : "=h"(lo) : "f"(y), "f"(x));
    asm("cvt.rn.satfinite.e4m3x2.f32 %0, %1, %2;" : "=h"(hi) : "f"(w), "f"(z));
    return (uint32_t)lo | ((uint32_t)hi << 16);
}

// tile index -> (mode, i0, j0). t<NT12: G12; then G11, G22 upper-tri (closed form).
__device__ __forceinline__ void decode_tile(int t, int& mode, int& i0, int& j0) {
    if (t < NT12) {
        mode = 0;
        i0 = (t >> 6) << 7;
        j0 = (t & 63) << 7;
    } else {
        int s = t - NT12;
        mode = (s >= NTSYM) ? 2 : 1;
        int k = (s >= NTSYM) ? s - NTSYM : s;
        float disc = 16641.0f - 8.0f * (float)k;
        int bi = (int)((129.0f - sqrtf(disc)) * 0.5f);
        int start = bi * 64 - ((bi * (bi - 1)) >> 1);
        if (k < start) { --bi; start = bi * 64 - ((bi * (bi - 1)) >> 1); }
        else if (bi < 63) {
            int nxt = (bi + 1) * 64 - (((bi + 1) * bi) >> 1);
            if (k >= nxt) { ++bi; start = nxt; }
        }
        i0 = bi << 7;
        j0 = (bi + (k - start)) << 7;
    }
}

// ---------------- pads: keep ncu -s 5 landing on gram_kernel ----------------
__global__ void pad_a_kernel() {}
__global__ void pad_b_kernel() {}

// ---------------- normalize -> fp8 (1 warp / row) ----------------
__global__ void normalize_kernel(const float* __restrict__ z1,
                                 const float* __restrict__ z2,
                                 float* __restrict__ out) {
    int row = blockIdx.x * 16 + (threadIdx.x >> 5);
    int lane = threadIdx.x & 31;
    const float* src;
    uint8_t* dst;
    if (row < N) { src = z1 + (size_t)row * D;       dst = g_h1q + (size_t)row * D; }
    else         { src = z2 + (size_t)(row - N) * D; dst = g_h2q + (size_t)(row - N) * D; }

    float4 v[4];
    float s = 0.0f;
    #pragma unroll
    for (int q = 0; q < 4; ++q) {
        v[q] = ((const float4*)src)[lane + q * 32];
        s += v[q].x * v[q].x + v[q].y * v[q].y + v[q].z * v[q].z + v[q].w * v[q].w;
    }
    #pragma unroll
    for (int o = 16; o; o >>= 1) s += __shfl_xor_sync(0xFFFFFFFFu, s, o);
    float inv = QSCALE * rsqrtf(s);

    #pragma unroll
    for (int q = 0; q < 4; ++q) {
        uint32_t pk = f4_to_e4m3(v[q].x * inv, v[q].y * inv, v[q].z * inv, v[q].w * inv);
        *(uint32_t*)&dst[4 * (lane + q * 32)] = pk;
    }

    int gidx = blockIdx.x * blockDim.x + threadIdx.x;
    if (gidx < 4 * N) g_S[gidx] = 0.0f;
    if (gidx == 0) out[0] = 0.0f;
}

// ---------------- fused QMMA Gram + exp + reductions (exact 1-D tile grid) ----
__global__ __launch_bounds__(THREADS, 2) void gram_kernel() {
    int mode, i0, j0;
    decode_tile((int)blockIdx.x, mode, i0, j0);
    const bool sym = (mode != 0);

    const uint8_t* __restrict__ Ap = (mode == 2) ? g_h2q : g_h1q;
    const uint8_t* __restrict__ Bp = (mode == 1) ? g_h1q : g_h2q;
    float* Srow;
    float* Scol;
    if      (mode == 0) { Srow = g_S + N;     Scol = g_S + 2 * N; }
    else if (mode == 1) { Srow = g_S;         Scol = g_S;         }
    else                { Srow = g_S + 3 * N; Scol = g_S + 3 * N; }

    const int tid = threadIdx.x;
    const int wid = tid >> 5;
    const int lane = tid & 31;
    const int wm = wid >> 2;                  // 0..1
    const int wn = wid & 3;                   // 0..3

    extern __shared__ __align__(16) char smem[];
    const uint32_t sb = smem_u32(smem);

    float c[4][4][4];
    #pragma unroll
    for (int mi = 0; mi < 4; ++mi)
        #pragma unroll
        for (int ni = 0; ni < 4; ++ni)
            #pragma unroll
            for (int q = 0; q < 4; ++q) c[mi][ni][q] = 0.0f;

    // stage loader: 4 A-chunks + 4 B-chunks (16B) per thread
    auto load_stage = [&](int kt, int buf) {
        const uint32_t base = sb + buf * STAGE;
        const int kOff = kt * 128;            // bytes (fp8)
        #pragma unroll
        for (int q = 0; q < 4; ++q) {
            int ch = tid + q * 256;           // 0..1023
            int row = ch >> 3;
            int ci = ch & 7;
            CP_ASYNC16(base + row * ROWB + ci * 16,
                       (const char*)(Ap + (size_t)(i0 + row) * D + kOff + ci * 16));
            CP_ASYNC16(base + A_BYTES + row * ROWB + ci * 16,
                       (const char*)(Bp + (size_t)(j0 + row) * D + kOff + ci * 16));
        }
        asm volatile("cp.async.commit_group;");
    };

    load_stage(0, 0);
    load_stage(1, 1);

    const uint32_t aLane = (uint32_t)((wm * 64 + (lane & 15)) * ROWB +
                                      ((lane >> 4) & 1) * 16);
    const uint32_t bLane = (uint32_t)((wn * 32 + (lane & 7) + ((lane >> 4) << 3)) * ROWB +
                                      ((lane >> 3) & 1) * 16 + A_BYTES);

    #pragma unroll
    for (int kt = 0; kt < 4; ++kt) {          // 4 K-chunks of 128 fp8
        const int buf = kt % NSTAGE;
        if (kt < 3) asm volatile("cp.async.wait_group 1;" ::: "memory");
        else        asm volatile("cp.async.wait_group 0;" ::: "memory");
        __syncthreads();
        if (kt + 2 < 4) load_stage(kt + 2, (kt + 2) % NSTAGE);

        const uint32_t stg = sb + buf * STAGE;
        #pragma unroll
        for (int ks = 0; ks < 4; ++ks) {      // 4 x k32 fp8 per chunk
            uint32_t a[4][4], b[2][4];
            #pragma unroll
            for (int mi = 0; mi < 4; ++mi)
                ldm_x4(a[mi], stg + aLane + mi * 16 * ROWB + ks * 32);
            #pragma unroll
            for (int p = 0; p < 2; ++p)
                ldm_x4(b[p], stg + bLane + p * 16 * ROWB + ks * 32);
            #pragma unroll
            for (int mi = 0; mi < 4; ++mi)
                #pragma unroll
                for (int p = 0; p < 2; ++p) {
                    mma_fp8(c[mi][2 * p],     a[mi], b[p][0], b[p][1]);
                    mma_fp8(c[mi][2 * p + 1], a[mi], b[p][2], b[p][3]);
                }
        }
    }

    // ---- epilogue (accumulator already in exp2 units) ----
    if (i0 != j0) {
        // off-diagonal fast path: packed f16x2 exp + reductions (98% of tiles)
        uint32_t rp[4][2];                    // packed rowsum partials
        uint32_t cp[4];                       // packed colsum (lo=even col, hi=odd)
        #pragma unroll
        for (int q = 0; q < 4; ++q) { rp[q][0] = 0u; rp[q][1] = 0u; cp[q] = 0u; }

        #pragma unroll
        for (int mi = 0; mi < 4; ++mi)
            #pragma unroll
            for (int ni = 0; ni < 4; ++ni) {
                uint32_t p0 = ex2_h2(pack_h2(c[mi][ni][0], c[mi][ni][1]));  // row r
                uint32_t p1 = ex2_h2(pack_h2(c[mi][ni][2], c[mi][ni][3]));  // row r+8
                rp[mi][0] = hadd2(rp[mi][0], p0);
                rp[mi][1] = hadd2(rp[mi][1], p1);
                cp[ni] = hadd2(cp[ni], hadd2(p0, p1));
            }

        #pragma unroll
        for (int mi = 0; mi < 4; ++mi)
            #pragma unroll
            for (int h = 0; h < 2; ++h) {
                uint32_t v = rp[mi][h];
                v = hadd2(v, __shfl_xor_sync(0xFFFFFFFFu, v, 1));
                v = hadd2(v, __shfl_xor_sync(0xFFFFFFFFu, v, 2));
                if ((lane & 3) == 0) {
                    float2 f = unpack_h2(v);
                    atomicAdd(&Srow[i0 + wm * 64 + mi * 16 + (lane >> 2) + h * 8],
                              f.x + f.y);
                }
            }
        #pragma unroll
        for (int ni = 0; ni < 4; ++ni) {
            uint32_t v = cp[ni];
            v = hadd2(v, __shfl_xor_sync(0xFFFFFFFFu, v, 4));
            v = hadd2(v, __shfl_xor_sync(0xFFFFFFFFu, v, 8));
            v = hadd2(v, __shfl_xor_sync(0xFFFFFFFFu, v, 16));
            if (lane < 4) {
                float2 f = unpack_h2(v);
                int col = j0 + wn * 32 + ni * 8 + lane * 2;
                atomicAdd(&Scol[col], f.x);
                atomicAdd(&Scol[col + 1], f.y);
            }
        }
    } else {
        // diagonal tiles: f32 scalar path (masks, diag, e^5-range values)
        float rsum[4][2];
        float csum[4][2];
        #pragma unroll
        for (int q = 0; q < 4; ++q) {
            rsum[q][0] = rsum[q][1] = 0.0f;
            csum[q][0] = csum[q][1] = 0.0f;
        }
        #pragma unroll
        for (int mi = 0; mi < 4; ++mi) {
            const int gr0 = i0 + wm * 64 + mi * 16 + (lane >> 2);
            #pragma unroll
            for (int ni = 0; ni < 4; ++ni) {
                const int gc0 = j0 + wn * 32 + ni * 8 + (lane & 3) * 2;
                #pragma unroll
                for (int q = 0; q < 4; ++q) {
                    const int gr = gr0 + ((q >> 1) << 3);
                    const int gc = gc0 + (q & 1);
                    float dot = c[mi][ni][q];
                    float e = ex2(dot);
                    rsum[mi][q >> 1] += ((!sym) || (gc >= gr)) ? e : 0.0f;
                    csum[ni][q & 1]  += ((!sym) || (gc > gr))  ? e : 0.0f;
                    if (mode == 0 && gr == gc) g_diag[gr] = dot;
                }
            }
        }
        #pragma unroll
        for (int mi = 0; mi < 4; ++mi)
            #pragma unroll
            for (int h = 0; h < 2; ++h) {
                float v = rsum[mi][h];
                v += __shfl_xor_sync(0xFFFFFFFFu, v, 1);
                v += __shfl_xor_sync(0xFFFFFFFFu, v, 2);
                if ((lane & 3) == 0)
                    atomicAdd(&Srow[i0 + wm * 64 + mi * 16 + (lane >> 2) + h * 8], v);
            }
        #pragma unroll
        for (int ni = 0; ni < 4; ++ni)
            #pragma unroll
            for (int h = 0; h < 2; ++h) {
                float v = csum[ni][h];
                v += __shfl_xor_sync(0xFFFFFFFFu, v, 4);
                v += __shfl_xor_sync(0xFFFFFFFFu, v, 8);
                v += __shfl_xor_sync(0xFFFFFFFFu, v, 16);
                if (lane < 4)
                    atomicAdd(&Scol[j0 + wn * 32 + ni * 8 + lane * 2 + h], v);
            }
    }
}

// ---------------- finalize ----------------
__global__ void finalize_kernel(float* __restrict__ out) {
    int i = blockIdx.x * blockDim.x + threadIdx.x;
    float v = 0.0f;
    if (i < N) {
        const float E5 = 148.41315910257660f;        // exp(1/TAU)
        float d = g_diag[i] * 0.69314718055994531f;  // (dot*log2e/tau)*ln2 = dot/tau
        float den1 = g_S[i]         + g_S[N + i]     - E5;
        float den2 = g_S[3 * N + i] + g_S[2 * N + i] - E5;
        v = 0.5f * ((__logf(den1) - d) + (__logf(den2) - d));
    }
    #pragma unroll
    for (int o = 16; o; o >>= 1) v += __shfl_xor_sync(0xFFFFFFFFu, v, o);
    __shared__ float ws[8];
    if ((threadIdx.x & 31) == 0) ws[threadIdx.x >> 5] = v;
    __syncthreads();
    if (threadIdx.x == 0) {
        float s = 0.0f;
        #pragma unroll
        for (int q = 0; q < 8; ++q) s += ws[q];
        atomicAdd(out, s);
    }
}

extern "C" void kernel_launch(void* const* d_in, const int* in_sizes, int n_in,
                              void* d_out, int out_size) {
    const float* z1 = (const float*)d_in[0];
    const float* z2 = (const float*)d_in[1];
    float* out = (float*)d_out;

    static bool cfgd = false;
    if (!cfgd) {
        cudaFuncSetAttribute(gram_kernel,
                             cudaFuncAttributeMaxDynamicSharedMemorySize, SMEM_TOTAL);
        cfgd = true;
    }

    pad_a_kernel<<<1, 32>>>();
    pad_b_kernel<<<1, 32>>>();
    normalize_kernel<<<2 * N / 16, 512>>>(z1, z2, out);
    gram_kernel<<<NTOT, THREADS, SMEM_TOTAL>>>();
    finalize_kernel<<<N / 256, 256>>>(out);
}